// round 16
// baseline (speedup 1.0000x reference)
#include <cuda_runtime.h>
#include <cuda_bf16.h>
#include <cuda_fp16.h>
#include <cstdint>

#define BB 4
#define HH 48
#define WW 48
#define CC 128

typedef unsigned int u32;
typedef unsigned long long u64;

// ---------------- scratch (device globals; no allocation allowed) ----------
// g_KVh / g_KVpool / g_kvbh hold MIXED types: bytes [0,256) of each 512-byte
// token row are bf16 K, bytes [256,512) are f16 V.
__device__ __nv_bfloat16 g_Fb [BB*HH*WW*CC];
__device__ __nv_bfloat16 g_FNb[BB*HH*WW*CC];
__device__ __nv_bfloat16 g_Wb [384*128];
__device__ __nv_bfloat16 g_Qb   [BB*HH*WW*CC];
__device__ __nv_bfloat16 g_KVh  [BB*HH*WW*256];
__device__ __nv_bfloat16 g_KVpool[BB*736*256];
__device__ __nv_bfloat16 g_kvbh [256];
__device__ float g_OP[2][BB*CC*HH*WW];              // partial out-proj per head-half

__device__ __forceinline__ u32 packbf(float lo, float hi) {
    u32 r; asm("cvt.rn.satfinite.bf16x2.f32 %0, %1, %2;" : "=r"(r) : "f"(hi), "f"(lo));
    return r;
}
__device__ __forceinline__ u32 packf16(float lo, float hi) {
    u32 r; asm("cvt.rn.f16x2.f32 %0, %1, %2;" : "=r"(r) : "f"(hi), "f"(lo));
    return r;
}
__device__ __forceinline__ u32 ex2h2(u32 x) {
    u32 r; asm("ex2.approx.f16x2 %0, %1;" : "=r"(r) : "r"(x)); return r;
}
__device__ __forceinline__ u32 hadd2(u32 a, u32 b) {
    u32 r; asm("add.rn.f16x2 %0, %1, %2;" : "=r"(r) : "r"(a), "r"(b)); return r;
}
__device__ __forceinline__ void h2tof(u32 v, float& lo, float& hi) {
    asm("{.reg .b16 l,h; mov.b32 {l,h}, %2; cvt.f32.f16 %0, l; cvt.f32.f16 %1, h;}"
        : "=f"(lo), "=f"(hi) : "r"(v));
}
__device__ __forceinline__ u64 ffma2(u64 a, u64 b, u64 c) {
    u64 d; asm("fma.rn.f32x2 %0,%1,%2,%3;" : "=l"(d) : "l"(a), "l"(b), "l"(c)); return d;
}
__device__ __forceinline__ void up2(u64 v, float& lo, float& hi) {
    asm("mov.b64 {%0,%1},%2;" : "=f"(lo), "=f"(hi) : "l"(v));
}
__device__ __forceinline__ void cp16(u32 dst, const void* src) {
    asm volatile("cp.async.cg.shared.global [%0], [%1], 16;" :: "r"(dst), "l"(src));
}
__device__ __forceinline__ void mma_bf16(float d[4], const u32 a[4], const u32 b[2]) {
    asm volatile(
        "mma.sync.aligned.m16n8k16.row.col.f32.bf16.bf16.f32 "
        "{%0,%1,%2,%3},{%4,%5,%6,%7},{%8,%9},{%0,%1,%2,%3};"
        : "+f"(d[0]), "+f"(d[1]), "+f"(d[2]), "+f"(d[3])
        : "r"(a[0]), "r"(a[1]), "r"(a[2]), "r"(a[3]), "r"(b[0]), "r"(b[1]));
}
__device__ __forceinline__ void mma_f16(float d[4], const u32 a[4], const u32 b[2]) {
    asm volatile(
        "mma.sync.aligned.m16n8k16.row.col.f32.f16.f16.f32 "
        "{%0,%1,%2,%3},{%4,%5,%6,%7},{%8,%9},{%0,%1,%2,%3};"
        : "+f"(d[0]), "+f"(d[1]), "+f"(d[2]), "+f"(d[3])
        : "r"(a[0]), "r"(a[1]), "r"(a[2]), "r"(a[3]), "r"(b[0]), "r"(b[1]));
}

// ============================================================================
// Kernel W: convert qw + kvw (fp32) -> g_Wb (bf16).
// ============================================================================
__global__ void kw_conv(const float* __restrict__ qw, const float* __restrict__ kvw) {
    int i = blockIdx.x * blockDim.x + threadIdx.x;
    if (i < 384*128)
        g_Wb[i] = __float2bfloat16(i < 16384 ? qw[i] : kvw[i - 16384]);
}

// ============================================================================
// Kernel 0 v2: coalesced NCHW transpose + LayerNorm -> bf16 raw + LN'd.
// ============================================================================
__global__ void __launch_bounds__(256)
k0_ln(const float* __restrict__ feat,
      const float* __restrict__ lnw, const float* __restrict__ lnb) {
    __shared__ float sA[64][129];
    __shared__ float sLw[128], sLb[128];
    __shared__ float sM[64], sR[64];

    int base = blockIdx.x * 64;
    int b    = base / 2304;
    int p0   = base % 2304;
    int tid  = threadIdx.x;

    if (tid < 128) { sLw[tid] = lnw[tid]; sLb[tid] = lnb[tid]; }

    const float* fb = feat + (size_t)b * CC * 2304 + p0;
#pragma unroll
    for (int i = 0; i < 32; i++) {
        int f = tid + i*256;
        int c = f >> 6, p = f & 63;
        sA[p][c] = fb[(size_t)c * 2304 + p];
    }
    __syncthreads();

    {
        int p = tid >> 2, tg = tid & 3;
        float s = 0.f, ss = 0.f;
#pragma unroll
        for (int k = 0; k < 32; k++) {
            float v = sA[p][tg*32 + k];
            s += v; ss += v*v;
        }
        s  += __shfl_xor_sync(0xffffffffu, s, 1);
        ss += __shfl_xor_sync(0xffffffffu, ss, 1);
        s  += __shfl_xor_sync(0xffffffffu, s, 2);
        ss += __shfl_xor_sync(0xffffffffu, ss, 2);
        float mean = s * (1.f/128.f);
        float var  = ss * (1.f/128.f) - mean*mean;
        if (tg == 0) { sM[p] = mean; sR[p] = rsqrtf(var + 1e-5f); }
    }
    __syncthreads();

    u32* dF = (u32*)g_Fb  + (size_t)base * 64;
    u32* dN = (u32*)g_FNb + (size_t)base * 64;
#pragma unroll
    for (int i = 0; i < 16; i++) {
        int f = tid + i*256;
        int p = f >> 6, col = f & 63;
        float v0 = sA[p][2*col], v1 = sA[p][2*col+1];
        float m = sM[p], r = sR[p];
        float n0 = (v0 - m)*r*sLw[2*col]   + sLb[2*col];
        float n1 = (v1 - m)*r*sLw[2*col+1] + sLb[2*col+1];
        dF[(size_t)p*64 + col] = packbf(v0, v1);
        dN[(size_t)p*64 + col] = packbf(n0, n1);
    }
}

// ============================================================================
// Kernel 1 v2: HMMA bf16 projection GEMMs.  sub 2 (V) packs f16.
// ============================================================================
#define K1SMEM ((64*65 + 128*65)*4 + 512)

__global__ void __launch_bounds__(256)
k1_gemm(const float* __restrict__ qb, const float* __restrict__ kvb) {
    extern __shared__ u32 dsu[];
    u32* sAu = dsu;
    u32* sWu = dsu + 64*65;
    float* sBias = (float*)(dsu + 64*65 + 128*65);

    int sub   = blockIdx.y;
    int mBase = blockIdx.x * 64;
    int tid   = threadIdx.x;
    int lane  = tid & 31;
    int warp  = tid >> 5;
    int mw = warp & 3, nh = warp >> 2;
    int t4 = lane & 3, g4 = lane >> 2;

    const u32* A  = (const u32*)((sub == 0) ? g_FNb : g_Fb);
    const u32* Wm = (const u32*)g_Wb + (size_t)sub * 8192;
    const float* bias = (sub == 0) ? qb : (kvb + (sub-1)*128);

    if (tid < 128) sBias[tid] = bias[tid];
#pragma unroll
    for (int i = 0; i < 16; i++) {
        int f = tid + i*256;
        int row = f >> 6, col = f & 63;
        sAu[row*65 + col] = A[(size_t)(mBase + row)*64 + col];
    }
#pragma unroll
    for (int i = 0; i < 32; i++) {
        int f = tid + i*256;
        int row = f >> 6, col = f & 63;
        sWu[row*65 + col] = Wm[(size_t)row*64 + col];
    }
    __syncthreads();

    u32 aA[8][4];
    {
        const u32* r0 = sAu + (mw*16 + g4)*65;
        const u32* r1 = sAu + (mw*16 + g4 + 8)*65;
#pragma unroll
        for (int s = 0; s < 8; s++) {
            aA[s][0] = r0[8*s + t4];
            aA[s][1] = r1[8*s + t4];
            aA[s][2] = r0[8*s + t4 + 4];
            aA[s][3] = r1[8*s + t4 + 4];
        }
    }

    float acc[8][4];
#pragma unroll
    for (int n = 0; n < 8; n++)
#pragma unroll
        for (int i = 0; i < 4; i++) acc[n][i] = 0.f;

#pragma unroll
    for (int n = 0; n < 8; n++) {
        const u32* wr = sWu + (nh*64 + n*8 + g4)*65;
#pragma unroll
        for (int s = 0; s < 8; s++) {
            u32 bW[2] = { wr[8*s + t4], wr[8*s + t4 + 4] };
            mma_bf16(acc[n], aA[s], bW);
        }
    }

    const float SC = 0.25f * 1.4426950408889634f;
    float sc = (sub == 0) ? SC : 1.f;
    int row0 = mBase + mw*16 + g4;
    u32* dst = (sub == 0) ? ((u32*)g_Qb) : ((u32*)g_KVh);
    int rstride = (sub == 0) ? 64 : 128;
    int cbase   = (sub == 0) ? 0  : (sub-1)*64;
#pragma unroll
    for (int n = 0; n < 8; n++) {
        int cn = nh*64 + n*8 + 2*t4;
        float b0 = sBias[cn], b1 = sBias[cn+1];
        float v00 = (acc[n][0] + b0)*sc, v01 = (acc[n][1] + b1)*sc;
        float v10 = (acc[n][2] + b0)*sc, v11 = (acc[n][3] + b1)*sc;
        u32 pk0, pk1;
        if (sub == 2) { pk0 = packf16(v00, v01); pk1 = packf16(v10, v11); }
        else          { pk0 = packbf (v00, v01); pk1 = packbf (v10, v11); }
        int ucol = cbase + nh*32 + n*4 + t4;
        dst[(size_t)row0*rstride + ucol]     = pk0;
        dst[(size_t)(row0+8)*rstride + ucol] = pk1;
    }
}

// ============================================================================
// Kernel 2: pooled KV into unified pool (K bf16 | V f16) + bias token.
// ============================================================================
__global__ void k2_pool(const float* __restrict__ kvb) {
    int t = blockIdx.x;
    int c = threadIdx.x;
    if (t < BB*576) {
        int b = t / 576, r = t % 576, my = r / 24, mx = r % 24;
        size_t p0 = (size_t)((b*48 + my*2)*48 + mx*2)*256 + c;
        size_t dp = ((size_t)(b*736 + r))*256 + c;
        if (c < 128) {
            const __nv_bfloat16* s = g_KVh + p0;
            float v = __bfloat162float(s[0]) + __bfloat162float(s[256])
                    + __bfloat162float(s[48*256]) + __bfloat162float(s[48*256+256]);
            g_KVpool[dp] = __float2bfloat16(v * 0.25f);
        } else {
            const __half* s = (const __half*)g_KVh + p0;
            float v = __half2float(s[0]) + __half2float(s[256])
                    + __half2float(s[48*256]) + __half2float(s[48*256+256]);
            ((__half*)g_KVpool)[dp] = __float2half(v * 0.25f);
        }
    } else if (t < BB*576 + BB*144) {
        int t2 = t - BB*576;
        int b = t2 / 144, r = t2 % 144, gy = r / 12, gx = r % 12;
        size_t dp = ((size_t)(b*736 + 576 + r))*256 + c;
        float v = 0.f;
        if (c < 128) {
#pragma unroll
            for (int i = 0; i < 4; i++)
#pragma unroll
                for (int j = 0; j < 4; j++)
                    v += __bfloat162float(
                        g_KVh[((size_t)((b*48 + gy*4 + i)*48 + gx*4 + j))*256 + c]);
            g_KVpool[dp] = __float2bfloat16(v * (1.f/16.f));
        } else {
#pragma unroll
            for (int i = 0; i < 4; i++)
#pragma unroll
                for (int j = 0; j < 4; j++)
                    v += __half2float(((const __half*)g_KVh)
                        [((size_t)((b*48 + gy*4 + i)*48 + gx*4 + j))*256 + c]);
            ((__half*)g_KVpool)[dp] = __float2half(v * (1.f/16.f));
        }
    } else {
        if (c < 128) g_kvbh[c] = __float2bfloat16(kvb[c]);
        else         ((__half*)g_kvbh)[c] = __float2half(kvb[c]);
    }
}

// ============================================================================
// Kernel 3 v13b: head-split for 2 CTAs/SM (R15 with 16B-aligned epilogue
// row stride 68 floats = 272 B).
// ============================================================================
#define NSTEP 31
#define ROWB 264
#define SLOTB (32*ROWB)
#define SMEMB (4*SLOTB*2)           // 67584 B
#define EST 68                      // epilogue row stride (floats), 272B = 17*16

__global__ void __launch_bounds__(256, 2)
k3_attn(const float* __restrict__ ow, const float* __restrict__ ob) {
    extern __shared__ float ds[];
    __nv_bfloat16* dsh = (__nv_bfloat16*)ds;

    int hh  = blockIdx.x & 1;
    int grp = blockIdx.x >> 1;
    int b = grp / 36, g = grp % 36;
    int gy = g / 6, gx = g % 6;
    int tid  = threadIdx.x;
    int lane = tid & 31;
    int warp = tid >> 5;
    int h  = hh*4 + (warp & 3);        // global head
    int mh = warp >> 2;                // query-half
    int t4 = lane & 3, g4 = lane >> 2;

    u32 aQ[2][4];
    {
        const u32* qp = (const u32*)g_Qb;
#pragma unroll
        for (int m = 0; m < 2; m++) {
            int wg = mh*2 + m;
            int wy = gy*2 + (wg>>1), wx = gx*2 + (wg&1);
            int qa = g4,     pya = wy*4 + (qa>>2), pxa = wx*4 + (qa&3);
            int qb2 = g4+8,  pyb = wy*4 + (qb2>>2), pxb = wx*4 + (qb2&3);
            size_t pa = (size_t)((b*48+pya)*48+pxa)*64 + h*8 + t4;
            size_t pb = (size_t)((b*48+pyb)*48+pxb)*64 + h*8 + t4;
            aQ[m][0] = qp[pa];     aQ[m][1] = qp[pb];
            aQ[m][2] = qp[pa+4];   aQ[m][3] = qp[pb+4];
        }
    }

    float o[2][2][4];
#pragma unroll
    for (int m = 0; m < 2; m++)
#pragma unroll
        for (int n = 0; n < 2; n++)
#pragma unroll
            for (int i = 0; i < 4; i++) o[m][n][i] = 0.f;
    u32 lsh[2][2] = {{0u,0u},{0u,0u}};

    // staging: 256 threads x 4 chunks of 16B per step (2 tiles)
    auto stage = [&](int s) {
#pragma unroll
        for (int c2 = 0; c2 < 4; c2++) {
            int flat = tid + c2*256;
            int tsel = flat >> 9;
            int row  = (flat >> 5) & 15;
            int ch   = flat & 31;
            int tt = 2*s + tsel;
            const char* src;
            if (tt < 16) {
                int wgl = tt >> 2, st = tt & 3;
                int id2 = st*16 + row;
                int y = (gy*2 + (wgl>>1))*4 + (id2>>3) - 2;
                int x = (gx*2 + (wgl&1))*4  + (id2&7)  - 2;
                src = ((unsigned)y < 48u && (unsigned)x < 48u)
                    ? (const char*)(g_KVh + ((size_t)((b*48+y)*48+x))*256)
                    : (const char*)g_kvbh;
            } else {
                src = (const char*)(g_KVpool
                      + ((size_t)(b*736) + (tt-16)*16 + row)*256);
            }
            u32 dst = (u32)__cvta_generic_to_shared(
                dsh + (size_t)(s&3)*SLOTB + (tsel*16 + row)*ROWB) + ch*16;
            cp16(dst, src + ch*16);
        }
        asm volatile("cp.async.commit_group;");
    };

    auto compute = [&](const __nv_bfloat16* tile, int tt) {
        int m0 = 0, m1 = 2;
        if (tt < 16) {
            int wgl = tt >> 2;
            if ((wgl >> 1) != mh) return;
            m0 = wgl & 1; m1 = m0 + 1;
        }
        u32 bK[2][2];
#pragma unroll
        for (int n = 0; n < 2; n++) {
            const u32* kp = (const u32*)(tile + (n*8 + g4)*ROWB) + h*8 + t4;
            bK[n][0] = kp[0];
            bK[n][1] = kp[4];
        }
        u32 bV[2][2];
#pragma unroll
        for (int vd = 0; vd < 2; vd++) {
            int col = 128 + h*16 + vd*8 + g4;
            u32 l0 = (u32)*(const unsigned short*)(tile + (2*t4  )*ROWB + col);
            u32 h0 = (u32)*(const unsigned short*)(tile + (2*t4+1)*ROWB + col);
            u32 l1 = (u32)*(const unsigned short*)(tile + (2*t4+8)*ROWB + col);
            u32 h1 = (u32)*(const unsigned short*)(tile + (2*t4+9)*ROWB + col);
            bV[vd][0] = l0 | (h0 << 16);
            bV[vd][1] = l1 | (h1 << 16);
        }
        for (int m = m0; m < m1; m++) {
            u32 aP[4];
#pragma unroll
            for (int n = 0; n < 2; n++) {
                float S[4];
#pragma unroll
                for (int i = 0; i < 4; i++) S[i] = 0.f;
                mma_bf16(S, aQ[m], bK[n]);
                u32 p01 = ex2h2(packf16(S[0], S[1]));
                u32 p23 = ex2h2(packf16(S[2], S[3]));
                lsh[m][0] = hadd2(lsh[m][0], p01);
                lsh[m][1] = hadd2(lsh[m][1], p23);
                aP[2*n]   = p01;
                aP[2*n+1] = p23;
            }
#pragma unroll
            for (int vd = 0; vd < 2; vd++)
                mma_f16(o[m][vd], aP, bV[vd]);
        }
    };

    stage(0);
    stage(1);
    for (int s = 0; s < NSTEP; s++) {
        if (s < NSTEP-1) {
            asm volatile("cp.async.wait_group 1;");
        } else {
            asm volatile("cp.async.wait_group 0;");
        }
        __syncthreads();
        if (s + 2 < NSTEP) stage(s+2);

        const __nv_bfloat16* buf = dsh + (size_t)(s&3)*SLOTB;
        int t0 = 2*s;
        compute(buf, t0);
        if (t0 + 1 < 61) compute(buf + 16*ROWB, t0 + 1);
    }
    __syncthreads();

    // ---- finalize ls ----
    float ls[2][2];
#pragma unroll
    for (int m = 0; m < 2; m++)
#pragma unroll
        for (int r = 0; r < 2; r++) {
            float lo, hi;
            h2tof(lsh[m][r], lo, hi);
            float v = lo + hi;
            v += __shfl_xor_sync(0xffffffffu, v, 1);
            v += __shfl_xor_sync(0xffffffffu, v, 2);
            ls[m][r] = v;
        }

    // ---- normalize O frags -> att smem (64 q x 64 cols for this head-half)
    float* att = ds;                    // [64][EST]
    float* wsm = ds + 64*EST;           // [64][EST]
#pragma unroll
    for (int m = 0; m < 2; m++) {
        float inv0 = 1.f / ls[m][0];
        float inv1 = 1.f / ls[m][1];
        int r0 = mh*32 + m*16 + g4;
        int hl = warp & 3;              // head-local column block
#pragma unroll
        for (int n = 0; n < 2; n++) {
            int col = hl*16 + n*8 + 2*t4;
            *(float2*)&att[r0*EST + col]     = make_float2(o[m][n][0]*inv0, o[m][n][1]*inv0);
            *(float2*)&att[(r0+8)*EST + col] = make_float2(o[m][n][2]*inv1, o[m][n][3]*inv1);
        }
    }
    __syncthreads();

    // ---- partial out projection: K = this CTA's 64 att columns ----
    // thread = (aqi = tid>>2 [64 q], og = tid&3); 2 chunks of 64 out rows.
    int aqi = tid >> 2, og = tid & 3;
    {
        int qi = aqi & 15, wq = aqi >> 4;
        int wy = gy*2 + (wq>>1), wx = gx*2 + (wq&1);
        int py = wy*4 + (qi>>2), px = wx*4 + (qi&3);
        float* OP = g_OP[hh];

#pragma unroll 1
        for (int c2 = 0; c2 < 2; c2++) {
            // stage ow rows [c2*64, +64), cols [hh*64, +64): 1024 float4
#pragma unroll
            for (int i = 0; i < 4; i++) {
                int f = tid + i*256;
                int row = f >> 4, quad = f & 15;
                *(float4*)&wsm[row*EST + quad*4] =
                    *(const float4*)(ow + (size_t)(c2*64 + row)*128 + hh*64 + quad*4);
            }
            __syncthreads();

            u64 r[16];
#pragma unroll
            for (int u2 = 0; u2 < 16; u2++) r[u2] = 0ull;
#pragma unroll 2
            for (int k4 = 0; k4 < 16; k4++) {
                longlong2 av = *(const longlong2*)&att[aqi*EST + k4*4];
#pragma unroll
                for (int u2 = 0; u2 < 16; u2++) {
                    longlong2 wv = *(const longlong2*)&wsm[(u2*4+og)*EST + k4*4];
                    r[u2] = ffma2((u64)av.x, (u64)wv.x, r[u2]);
                    r[u2] = ffma2((u64)av.y, (u64)wv.y, r[u2]);
                }
            }
#pragma unroll
            for (int u2 = 0; u2 < 16; u2++) {
                float a, bb;
                up2(r[u2], a, bb);
                int oc = c2*64 + u2*4 + og;
                float v = a + bb;
                if (hh == 0) v += ob[oc];
                OP[(((size_t)b*128 + oc)*48 + py)*48 + px] = v;
            }
            __syncthreads();
        }
    }
}

// ============================================================================
// Kernel 4: merge partials + residual.
// ============================================================================
__global__ void k4_merge(const float* __restrict__ feat, float* __restrict__ out) {
    int i = blockIdx.x * blockDim.x + threadIdx.x;
    const float4 a = ((const float4*)g_OP[0])[i];
    const float4 c = ((const float4*)g_OP[1])[i];
    const float4 f = ((const float4*)feat)[i];
    float4 r;
    r.x = a.x + c.x + f.x;
    r.y = a.y + c.y + f.y;
    r.z = a.z + c.z + f.z;
    r.w = a.w + c.w + f.w;
    ((float4*)out)[i] = r;
}

// ============================================================================
extern "C" void kernel_launch(void* const* d_in, const int* in_sizes, int n_in,
                              void* d_out, int out_size) {
    const float* feat = (const float*)d_in[0];
    const float* lnw  = (const float*)d_in[1];
    const float* lnb  = (const float*)d_in[2];
    const float* qw   = (const float*)d_in[3];
    const float* qb   = (const float*)d_in[4];
    const float* kvw  = (const float*)d_in[5];
    const float* kvb  = (const float*)d_in[6];
    const float* ow   = (const float*)d_in[7];
    const float* ob   = (const float*)d_in[8];
    float* out = (float*)d_out;

    cudaFuncSetAttribute(k1_gemm, cudaFuncAttributeMaxDynamicSharedMemorySize, K1SMEM);
    cudaFuncSetAttribute(k3_attn, cudaFuncAttributeMaxDynamicSharedMemorySize, SMEMB);

    kw_conv<<<192, 256>>>(qw, kvw);
    k0_ln<<<144, 256>>>(feat, lnw, lnb);
    k1_gemm<<<dim3(144, 3), 256, K1SMEM>>>(qb, kvb);
    k2_pool<<<2881, 256>>>(kvb);
    k3_attn<<<288, 256, SMEMB>>>(ow, ob);
    k4_merge<<<1152, 256>>>(feat, out);
}